// round 13
// baseline (speedup 1.0000x reference)
#include <cuda_runtime.h>

// Binned dense-grid trilerp.
//  Pass A: zero histogram; Pass B: histogram of (z0,y0)@res256 keys (65536 bins);
//  Pass C: single-block exclusive scan; Pass D: scatter -> g_perm (sorted point order);
//  Pass E: 8-lane gather kernel processing points in bin order (cb4/cb3 accesses
//          become spatially local -> L2 captures reuse, DRAM ~sequential).
// Per-point math identical regardless of perm order -> deterministic output.

#define MAXN 2000000
#define NBINS 65536

__device__ int g_hist[NBINS];
__device__ int g_off[NBINS];
__device__ int g_perm[MAXN];

__device__ __forceinline__ int bin_key(const float* __restrict__ pts, int pt)
{
    float py = pts[3 * pt + 1];
    float pz = pts[3 * pt + 2];
    int y0 = min((int)(py * 255.0f), 254);
    int z0 = min((int)(pz * 255.0f), 254);
    return z0 * 256 + y0;
}

__global__ void __launch_bounds__(256) zero_hist()
{
    int i = blockIdx.x * blockDim.x + threadIdx.x;
    if (i < NBINS) g_hist[i] = 0;
}

__global__ void __launch_bounds__(256) hist_kernel(const float* __restrict__ pts, int n)
{
    int i = blockIdx.x * blockDim.x + threadIdx.x;
    if (i < n) atomicAdd(&g_hist[bin_key(pts, i)], 1);
}

__global__ void __launch_bounds__(1024) scan_kernel()
{
    __shared__ int tmp[1024];
    int t = threadIdx.x;
    int base = t * (NBINS / 1024);   // 64 bins per thread

    int sum = 0;
    #pragma unroll 4
    for (int j = 0; j < NBINS / 1024; ++j) sum += g_hist[base + j];

    tmp[t] = sum;
    __syncthreads();
    for (int off = 1; off < 1024; off <<= 1) {
        int v = (t >= off) ? tmp[t - off] : 0;
        __syncthreads();
        tmp[t] += v;
        __syncthreads();
    }
    int run = tmp[t] - sum;          // exclusive prefix of this thread's chunk

    #pragma unroll 4
    for (int j = 0; j < NBINS / 1024; ++j) {
        int c = g_hist[base + j];
        g_off[base + j] = run;
        run += c;
    }
}

__global__ void __launch_bounds__(256) scatter_kernel(const float* __restrict__ pts, int n)
{
    int i = blockIdx.x * blockDim.x + threadIdx.x;
    if (i < n) {
        int pos = atomicAdd(&g_off[bin_key(pts, i)], 1);
        g_perm[pos] = i;
    }
}

// ---------------- main gather kernel (8 lanes per point) ----------------

// HINT: 0 = plain nc, 1 = L2::evict_last (cb3), 2 = L2::evict_first (cb4)
template<int HINT>
__device__ __forceinline__ void ld_corner256(const float* __restrict__ p, float* v)
{
    unsigned r0, r1, r2, r3, r4, r5, r6, r7;
    if (HINT == 1) {
        asm("ld.global.nc.L2::evict_last.v8.b32 {%0,%1,%2,%3,%4,%5,%6,%7}, [%8];"
            : "=r"(r0), "=r"(r1), "=r"(r2), "=r"(r3),
              "=r"(r4), "=r"(r5), "=r"(r6), "=r"(r7) : "l"(p));
    } else if (HINT == 2) {
        asm("ld.global.nc.L2::evict_first.v8.b32 {%0,%1,%2,%3,%4,%5,%6,%7}, [%8];"
            : "=r"(r0), "=r"(r1), "=r"(r2), "=r"(r3),
              "=r"(r4), "=r"(r5), "=r"(r6), "=r"(r7) : "l"(p));
    } else {
        asm("ld.global.nc.v8.b32 {%0,%1,%2,%3,%4,%5,%6,%7}, [%8];"
            : "=r"(r0), "=r"(r1), "=r"(r2), "=r"(r3),
              "=r"(r4), "=r"(r5), "=r"(r6), "=r"(r7) : "l"(p));
    }
    v[0] = __uint_as_float(r0); v[1] = __uint_as_float(r1);
    v[2] = __uint_as_float(r2); v[3] = __uint_as_float(r3);
    v[4] = __uint_as_float(r4); v[5] = __uint_as_float(r5);
    v[6] = __uint_as_float(r6); v[7] = __uint_as_float(r7);
}

template<int RES, int HINT>
__device__ __forceinline__ void lerp_add(const float* __restrict__ cb,
                                         float px, float py, float pz,
                                         int dx, int dy, int dz,
                                         float sx, float cx,
                                         float sy, float cy,
                                         float sz, float cz,
                                         float* acc)
{
    const float s = (float)(RES - 1);
    float x = px * s, y = py * s, z = pz * s;

    int x0 = min((int)x, RES - 2);
    int y0 = min((int)y, RES - 2);
    int z0 = min((int)z, RES - 2);

    float wx = fmaf(sx, x - (float)x0, cx);
    float wy = fmaf(sy, y - (float)y0, cy);
    float wz = fmaf(sz, z - (float)z0, cz);
    float w  = wx * wy * wz;

    int idx = (x0 + dx) + (y0 + dy) * RES + (z0 + dz) * (RES * RES);
    const float* p = cb + (size_t)idx * 8;

    float v[8];
    ld_corner256<HINT>(p, v);

    #pragma unroll
    for (int i = 0; i < 8; ++i)
        acc[i] = fmaf(w, v[i], acc[i]);
}

__device__ __forceinline__ float reduce_distribute(float* acc, int g)
{
    float t[4];
    {
        bool k = (g & 1);
        #pragma unroll
        for (int j = 0; j < 4; ++j) {
            float snd = k ? acc[2 * j] : acc[2 * j + 1];
            float rcv = __shfl_xor_sync(0xffffffffu, snd, 1);
            float kep = k ? acc[2 * j + 1] : acc[2 * j];
            t[j] = kep + rcv;
        }
    }
    float u[2];
    {
        bool k = (g >> 1) & 1;
        #pragma unroll
        for (int j = 0; j < 2; ++j) {
            float snd = k ? t[2 * j] : t[2 * j + 1];
            float rcv = __shfl_xor_sync(0xffffffffu, snd, 2);
            float kep = k ? t[2 * j + 1] : t[2 * j];
            u[j] = kep + rcv;
        }
    }
    {
        bool k = (g >> 2) & 1;
        float snd = k ? u[0] : u[1];
        float rcv = __shfl_xor_sync(0xffffffffu, snd, 4);
        float kep = k ? u[1] : u[0];
        return kep + rcv;
    }
}

__global__ void __launch_bounds__(256, 7) dense_grid_binned_kernel(
    const float* __restrict__ pts,
    const float* __restrict__ cb0,
    const float* __restrict__ cb1,
    const float* __restrict__ cb2,
    const float* __restrict__ cb3,
    const float* __restrict__ cb4,
    float* __restrict__ out,
    int n)
{
    int tid  = blockIdx.x * blockDim.x + threadIdx.x;
    int lane = threadIdx.x & 31;
    int g    = lane & 7;
    int slot = (tid >> 5) * 4 + (lane >> 3);   // sorted slot

    bool valid = (slot < n);
    int pt = valid ? g_perm[slot] : g_perm[0];

    float px = __ldg(&pts[3 * pt + 0]);
    float py = __ldg(&pts[3 * pt + 1]);
    float pz = __ldg(&pts[3 * pt + 2]);

    int dx = g & 1, dy = (g >> 1) & 1, dz = g >> 2;
    float sx = dx ? 1.0f : -1.0f, cx = dx ? 0.0f : 1.0f;
    float sy = dy ? 1.0f : -1.0f, cy = dy ? 0.0f : 1.0f;
    float sz = dz ? 1.0f : -1.0f, cz = dz ? 0.0f : 1.0f;

    float acc[8];
    #pragma unroll
    for (int i = 0; i < 8; ++i) acc[i] = 0.0f;

    lerp_add< 16, 0>(cb0, px, py, pz, dx, dy, dz, sx, cx, sy, cy, sz, cz, acc);
    lerp_add< 32, 0>(cb1, px, py, pz, dx, dy, dz, sx, cx, sy, cy, sz, cz, acc);
    lerp_add< 64, 0>(cb2, px, py, pz, dx, dy, dz, sx, cx, sy, cy, sz, cz, acc);
    lerp_add<128, 1>(cb3, px, py, pz, dx, dy, dz, sx, cx, sy, cy, sz, cz, acc);
    lerp_add<256, 2>(cb4, px, py, pz, dx, dy, dz, sx, cx, sy, cy, sz, cz, acc);

    float r = reduce_distribute(acc, g);

    if (valid)
        out[(size_t)pt * 8 + g] = r;
}

extern "C" void kernel_launch(void* const* d_in, const int* in_sizes, int n_in,
                              void* d_out, int out_size)
{
    const float* pts = (const float*)d_in[0];
    const float* cb0 = (const float*)d_in[1];
    const float* cb1 = (const float*)d_in[2];
    const float* cb2 = (const float*)d_in[3];
    const float* cb3 = (const float*)d_in[4];
    const float* cb4 = (const float*)d_in[5];
    float* out = (float*)d_out;

    int n = in_sizes[0] / 3;                 // pts is [N,3]

    zero_hist<<<(NBINS + 255) / 256, 256>>>();
    hist_kernel<<<(n + 255) / 256, 256>>>(pts, n);
    scan_kernel<<<1, 1024>>>();
    scatter_kernel<<<(n + 255) / 256, 256>>>(pts, n);

    int total_threads = ((n + 3) / 4) * 32;  // 8 lanes/pt, 4 pts/warp
    int blocks = (total_threads + 255) / 256;
    dense_grid_binned_kernel<<<blocks, 256>>>(pts, cb0, cb1, cb2, cb3, cb4, out, n);
}

// round 14
// speedup vs baseline: 1.4972x; 1.4972x over previous
#include <cuda_runtime.h>

// R12 base (262.0us best) + streaming hints on ALL one-shot traffic:
//   pts  -> __ldcs (read once), out -> __stcs (written once, never re-read),
//   cb2/cb3 -> L2::evict_last (pinned reuse set, 72MB < L2),
//   cb4 -> L2::evict_first (512MB pure stream).
// Structure unchanged: 8 lanes/pt, lane g owns corner (g&1,(g>>1)&1,g>>2),
// one LDG.256 per lane per level, butterfly reduce-distribute -> lane g = feat g.

// HINT: 0 = plain nc, 1 = L2::evict_last, 2 = L2::evict_first
template<int HINT>
__device__ __forceinline__ void ld_corner256(const float* __restrict__ p, float* v)
{
    unsigned r0, r1, r2, r3, r4, r5, r6, r7;
    if (HINT == 1) {
        asm("ld.global.nc.L2::evict_last.v8.b32 {%0,%1,%2,%3,%4,%5,%6,%7}, [%8];"
            : "=r"(r0), "=r"(r1), "=r"(r2), "=r"(r3),
              "=r"(r4), "=r"(r5), "=r"(r6), "=r"(r7) : "l"(p));
    } else if (HINT == 2) {
        asm("ld.global.nc.L2::evict_first.v8.b32 {%0,%1,%2,%3,%4,%5,%6,%7}, [%8];"
            : "=r"(r0), "=r"(r1), "=r"(r2), "=r"(r3),
              "=r"(r4), "=r"(r5), "=r"(r6), "=r"(r7) : "l"(p));
    } else {
        asm("ld.global.nc.v8.b32 {%0,%1,%2,%3,%4,%5,%6,%7}, [%8];"
            : "=r"(r0), "=r"(r1), "=r"(r2), "=r"(r3),
              "=r"(r4), "=r"(r5), "=r"(r6), "=r"(r7) : "l"(p));
    }
    v[0] = __uint_as_float(r0); v[1] = __uint_as_float(r1);
    v[2] = __uint_as_float(r2); v[3] = __uint_as_float(r3);
    v[4] = __uint_as_float(r4); v[5] = __uint_as_float(r5);
    v[6] = __uint_as_float(r6); v[7] = __uint_as_float(r7);
}

template<int RES, int HINT>
__device__ __forceinline__ void lerp_add(const float* __restrict__ cb,
                                         float px, float py, float pz,
                                         int dx, int dy, int dz,
                                         float sx, float cx,
                                         float sy, float cy,
                                         float sz, float cz,
                                         float* acc)
{
    const float s = (float)(RES - 1);
    float x = px * s, y = py * s, z = pz * s;

    // pts in [0,1) -> coords >= 0 -> trunc == floor; clamp upper in int
    int x0 = min((int)x, RES - 2);
    int y0 = min((int)y, RES - 2);
    int z0 = min((int)z, RES - 2);

    // d ? f : 1-f == fma(s, f, c), s=+/-1, c=0/1 (hoisted per lane)
    float wx = fmaf(sx, x - (float)x0, cx);
    float wy = fmaf(sy, y - (float)y0, cy);
    float wz = fmaf(sz, z - (float)z0, cz);
    float w  = wx * wy * wz;

    int idx = (x0 + dx) + (y0 + dy) * RES + (z0 + dz) * (RES * RES);
    const float* p = cb + (size_t)idx * 8;

    float v[8];
    ld_corner256<HINT>(p, v);

    #pragma unroll
    for (int i = 0; i < 8; ++i)
        acc[i] = fmaf(w, v[i], acc[i]);
}

__device__ __forceinline__ float reduce_distribute(float* acc, int g)
{
    float t[4];
    {
        bool k = (g & 1);
        #pragma unroll
        for (int j = 0; j < 4; ++j) {
            float snd = k ? acc[2 * j] : acc[2 * j + 1];
            float rcv = __shfl_xor_sync(0xffffffffu, snd, 1);
            float kep = k ? acc[2 * j + 1] : acc[2 * j];
            t[j] = kep + rcv;
        }
    }
    float u[2];
    {
        bool k = (g >> 1) & 1;
        #pragma unroll
        for (int j = 0; j < 2; ++j) {
            float snd = k ? t[2 * j] : t[2 * j + 1];
            float rcv = __shfl_xor_sync(0xffffffffu, snd, 2);
            float kep = k ? t[2 * j + 1] : t[2 * j];
            u[j] = kep + rcv;
        }
    }
    {
        bool k = (g >> 2) & 1;
        float snd = k ? u[0] : u[1];
        float rcv = __shfl_xor_sync(0xffffffffu, snd, 4);
        float kep = k ? u[1] : u[0];
        return kep + rcv;
    }
}

__global__ void __launch_bounds__(256, 7) dense_grid_8lane_kernel(
    const float* __restrict__ pts,
    const float* __restrict__ cb0,
    const float* __restrict__ cb1,
    const float* __restrict__ cb2,
    const float* __restrict__ cb3,
    const float* __restrict__ cb4,
    float* __restrict__ out,
    int n)
{
    int tid  = blockIdx.x * blockDim.x + threadIdx.x;
    int lane = threadIdx.x & 31;
    int g    = lane & 7;                      // corner id within 8-lane group
    int pt   = (tid >> 5) * 4 + (lane >> 3);  // 4 points per warp

    bool valid = (pt < n);
    int ptc = valid ? pt : (n - 1);

    // read-once stream: don't let pts allocate with normal priority in L2
    float px = __ldcs(&pts[3 * ptc + 0]);
    float py = __ldcs(&pts[3 * ptc + 1]);
    float pz = __ldcs(&pts[3 * ptc + 2]);

    int dx = g & 1, dy = (g >> 1) & 1, dz = g >> 2;

    float sx = dx ? 1.0f : -1.0f, cx = dx ? 0.0f : 1.0f;
    float sy = dy ? 1.0f : -1.0f, cy = dy ? 0.0f : 1.0f;
    float sz = dz ? 1.0f : -1.0f, cz = dz ? 0.0f : 1.0f;

    float acc[8];
    #pragma unroll
    for (int i = 0; i < 8; ++i) acc[i] = 0.0f;

    lerp_add< 16, 0>(cb0, px, py, pz, dx, dy, dz, sx, cx, sy, cy, sz, cz, acc);
    lerp_add< 32, 0>(cb1, px, py, pz, dx, dy, dz, sx, cx, sy, cy, sz, cz, acc);
    lerp_add< 64, 1>(cb2, px, py, pz, dx, dy, dz, sx, cx, sy, cy, sz, cz, acc);  // evict_last
    lerp_add<128, 1>(cb3, px, py, pz, dx, dy, dz, sx, cx, sy, cy, sz, cz, acc);  // evict_last
    lerp_add<256, 2>(cb4, px, py, pz, dx, dy, dz, sx, cx, sy, cy, sz, cz, acc);  // evict_first

    float r = reduce_distribute(acc, g);

    if (valid) {
        // write-once stream: avoid write-allocate pollution of the pinned set
        __stcs(&out[(size_t)pt * 8 + g], r);
    }
}

extern "C" void kernel_launch(void* const* d_in, const int* in_sizes, int n_in,
                              void* d_out, int out_size)
{
    const float* pts = (const float*)d_in[0];
    const float* cb0 = (const float*)d_in[1];
    const float* cb1 = (const float*)d_in[2];
    const float* cb2 = (const float*)d_in[3];
    const float* cb3 = (const float*)d_in[4];
    const float* cb4 = (const float*)d_in[5];
    float* out = (float*)d_out;

    int n = in_sizes[0] / 3;                 // pts is [N,3]
    int total_threads = ((n + 3) / 4) * 32;  // 8 lanes/pt, 4 pts/warp
    int threads = 256;
    int blocks = (total_threads + threads - 1) / threads;
    dense_grid_8lane_kernel<<<blocks, threads>>>(pts, cb0, cb1, cb2, cb3, cb4, out, n);
}